// round 9
// baseline (speedup 1.0000x reference)
#include <cuda_runtime.h>
#include <cuda_bf16.h>

// Scratch (no cudaMalloc allowed).
__device__ double             g_sum[3];
__device__ unsigned long long g_cnt[3];
__device__ float              g_mean[3];
// 2-bit classes packed 4 pixels/byte: max 16M pixels -> 4 MiB (L2-resident).
__device__ unsigned char      g_packed[4 * 1024 * 1024];

__global__ void zero_kernel() {
    if (threadIdx.x < 3) {
        g_sum[threadIdx.x] = 0.0;
        g_cnt[threadIdx.x] = 0ULL;
    }
}

// Reduce: per-class global sums + counts, and emit packed 2-bit classes.
__global__ void __launch_bounds__(256) reduce_kernel(
        const float4* __restrict__ feats4,
        const int4*  __restrict__ inst4,
        const float* __restrict__ feats,
        const int*   __restrict__ inst,
        int ngroups, int rem) {
    float s0 = 0.f, s1 = 0.f, s2 = 0.f;
    int   c0 = 0,   c1 = 0,   c2 = 0;

    const int tid    = blockIdx.x * blockDim.x + threadIdx.x;
    const int stride = gridDim.x * blockDim.x;

    for (int g = tid; g < ngroups; g += stride) {
        int4   ii = __ldcs(&inst4[(size_t)g]);             // evict-first; packed copy replaces it
        float4 a  = __ldcs(&feats4[(size_t)3 * g + 0]);    // evict-first: feats never reused
        float4 b  = __ldcs(&feats4[(size_t)3 * g + 1]);
        float4 c  = __ldcs(&feats4[(size_t)3 * g + 2]);

        // packed classes for scatter (normal store -> stays in L2)
        g_packed[g] = (unsigned char)(ii.x | (ii.y << 2) | (ii.z << 4) | (ii.w << 6));

        // pixel sums across the 3 channels
        float p0 = a.x + a.y + a.z;
        float p1 = a.w + b.x + b.y;
        float p2 = b.z + b.w + c.x;
        float p3 = c.y + c.z + c.w;

        s0 += (ii.x == 0) ? p0 : 0.f;  c0 += (ii.x == 0);
        s1 += (ii.x == 1) ? p0 : 0.f;  c1 += (ii.x == 1);
        s2 += (ii.x == 2) ? p0 : 0.f;  c2 += (ii.x == 2);

        s0 += (ii.y == 0) ? p1 : 0.f;  c0 += (ii.y == 0);
        s1 += (ii.y == 1) ? p1 : 0.f;  c1 += (ii.y == 1);
        s2 += (ii.y == 2) ? p1 : 0.f;  c2 += (ii.y == 2);

        s0 += (ii.z == 0) ? p2 : 0.f;  c0 += (ii.z == 0);
        s1 += (ii.z == 1) ? p2 : 0.f;  c1 += (ii.z == 1);
        s2 += (ii.z == 2) ? p2 : 0.f;  c2 += (ii.z == 2);

        s0 += (ii.w == 0) ? p3 : 0.f;  c0 += (ii.w == 0);
        s1 += (ii.w == 1) ? p3 : 0.f;  c1 += (ii.w == 1);
        s2 += (ii.w == 2) ? p3 : 0.f;  c2 += (ii.w == 2);
    }

    // scalar tail (npix % 4)
    if (tid < rem) {
        size_t p = (size_t)ngroups * 4 + tid;
        int cls = inst[p];
        float v = feats[3 * p + 0] + feats[3 * p + 1] + feats[3 * p + 2];
        s0 += (cls == 0) ? v : 0.f;  c0 += (cls == 0);
        s1 += (cls == 1) ? v : 0.f;  c1 += (cls == 1);
        s2 += (cls == 2) ? v : 0.f;  c2 += (cls == 2);
    }

    // warp reduce
    #pragma unroll
    for (int off = 16; off > 0; off >>= 1) {
        s0 += __shfl_down_sync(0xFFFFFFFFu, s0, off);
        s1 += __shfl_down_sync(0xFFFFFFFFu, s1, off);
        s2 += __shfl_down_sync(0xFFFFFFFFu, s2, off);
        c0 += __shfl_down_sync(0xFFFFFFFFu, c0, off);
        c1 += __shfl_down_sync(0xFFFFFFFFu, c1, off);
        c2 += __shfl_down_sync(0xFFFFFFFFu, c2, off);
    }

    __shared__ float sh_s[3][8];
    __shared__ int   sh_c[3][8];
    int lane = threadIdx.x & 31;
    int wid  = threadIdx.x >> 5;
    if (lane == 0) {
        sh_s[0][wid] = s0; sh_s[1][wid] = s1; sh_s[2][wid] = s2;
        sh_c[0][wid] = c0; sh_c[1][wid] = c1; sh_c[2][wid] = c2;
    }
    __syncthreads();

    if (threadIdx.x < 3) {
        int cls = threadIdx.x;
        float     fs = 0.f;
        long long ic = 0;
        int nwarps = blockDim.x >> 5;
        for (int w = 0; w < nwarps; w++) { fs += sh_s[cls][w]; ic += sh_c[cls][w]; }
        atomicAdd(&g_sum[cls], (double)fs);
        atomicAdd(&g_cnt[cls], (unsigned long long)ic);
    }
}

__global__ void finalize_kernel() {
    if (threadIdx.x < 3) {
        int c = threadIdx.x;
        double denom = 3.0 * (double)g_cnt[c];   // count includes the 3 channels
        g_mean[c] = (float)(g_sum[c] / denom);
    }
}

// Scatter: one float4 per thread per iteration -> fully coalesced STG.128
// (consecutive lanes write consecutive 16B; each store covers 4 full 128B lines).
// Classes come from the packed 2-bit array (4 MiB, L2-hot from reduce).
__global__ void __launch_bounds__(256) scatter_kernel(
        float4* __restrict__ out4,
        const int* __restrict__ inst,
        float* __restrict__ out,
        int nf4, int ngroups, int rem) {
    const float m0 = g_mean[0];
    const float m1 = g_mean[1];
    const float m2 = g_mean[2];

    const int tid    = blockIdx.x * blockDim.x + threadIdx.x;
    const int stride = gridDim.x * blockDim.x;

    for (int f = tid; f < nf4; f += stride) {
        int g = f / 3;                 // pixel-group (4 pixels, 12 floats, 3 float4s)
        int s = f - 3 * g;             // which float4 within the group: 0,1,2
        unsigned int b = g_packed[g];

        // float j of this float4 belongs to local pixel (4s + j) / 3
        int base = 4 * s;
        float v[4];
        #pragma unroll
        for (int j = 0; j < 4; j++) {
            int pl  = (base + j) / 3;                  // 0..3 (compile-time folded per j)
            int cls = (b >> (2 * pl)) & 3;
            v[j] = (cls == 0) ? m0 : ((cls == 1) ? m1 : m2);
        }
        __stcs(&out4[(size_t)f], make_float4(v[0], v[1], v[2], v[3]));
    }

    // scalar tail: pixels beyond 4*ngroups (not covered by g_packed)
    if (tid < rem) {
        size_t p = (size_t)ngroups * 4 + tid;
        int cls = inst[p];
        float m = (cls == 0) ? m0 : ((cls == 1) ? m1 : m2);
        out[3 * p + 0] = m;
        out[3 * p + 1] = m;
        out[3 * p + 2] = m;
    }
}

extern "C" void kernel_launch(void* const* d_in, const int* in_sizes, int n_in,
                              void* d_out, int out_size) {
    const float* feats = (const float*)d_in[0];
    const int*   inst  = (const int*)d_in[1];
    float*       out   = (float*)d_out;

    const int npix    = in_sizes[1];      // one inst entry per pixel
    const int ngroups = npix >> 2;        // groups of 4 pixels
    const int rem     = npix & 3;
    const int nf4     = 3 * ngroups;      // float4s covered by packed groups (exact)

    const int threads = 256;
    const int blocks  = 1216;             // 152 SMs * 8 CTAs; grid-stride covers the rest

    zero_kernel<<<1, 32>>>();
    reduce_kernel<<<blocks, threads>>>((const float4*)feats, (const int4*)inst,
                                       feats, inst, ngroups, rem);
    finalize_kernel<<<1, 32>>>();
    scatter_kernel<<<blocks, threads>>>((float4*)out, inst, out, nf4, ngroups, rem);
}

// round 15
// speedup vs baseline: 1.2604x; 1.2604x over previous
#include <cuda_runtime.h>
#include <cuda_bf16.h>

// Scratch (no cudaMalloc). Statically zero-initialized at module load;
// finalize_kernel re-zeroes accumulators after use so every graph replay
// starts from a clean state.
__device__ double             g_sum[3];
__device__ unsigned long long g_cnt[3];
__device__ float              g_mean[3];
// 2-bit classes packed 4 pixels/byte: max 16M pixels -> 4 MiB (L2-resident).
__device__ unsigned char      g_packed[4 * 1024 * 1024];

// Reduce: per-class global sums + counts, and emit packed 2-bit classes.
// Two groups per iteration, spaced `stride` apart: 8 independent LDG.128s
// in flight (MLP 8), each warp-coalesced.
__global__ void __launch_bounds__(256) reduce_kernel(
        const float4* __restrict__ feats4,
        const int4*  __restrict__ inst4,
        const float* __restrict__ feats,
        const int*   __restrict__ inst,
        int ngroups, int rem) {
    float s0 = 0.f, s1 = 0.f, s2 = 0.f;
    int   c0 = 0,   c1 = 0,   c2 = 0;

    const int tid     = blockIdx.x * blockDim.x + threadIdx.x;
    const int stride  = gridDim.x * blockDim.x;
    const int stride2 = 2 * stride;

    int base = tid;
    for (; base + stride < ngroups; base += stride2) {
        const int g1 = base, g2 = base + stride;
        // issue all 8 loads up front (independent -> MLP 8)
        int4   i1  = __ldcs(&inst4[(size_t)g1]);
        float4 fa1 = __ldcs(&feats4[(size_t)3 * g1 + 0]);
        float4 fb1 = __ldcs(&feats4[(size_t)3 * g1 + 1]);
        float4 fc1 = __ldcs(&feats4[(size_t)3 * g1 + 2]);
        int4   i2  = __ldcs(&inst4[(size_t)g2]);
        float4 fa2 = __ldcs(&feats4[(size_t)3 * g2 + 0]);
        float4 fb2 = __ldcs(&feats4[(size_t)3 * g2 + 1]);
        float4 fc2 = __ldcs(&feats4[(size_t)3 * g2 + 2]);

        g_packed[g1] = (unsigned char)(i1.x | (i1.y << 2) | (i1.z << 4) | (i1.w << 6));
        g_packed[g2] = (unsigned char)(i2.x | (i2.y << 2) | (i2.z << 4) | (i2.w << 6));

        float p0 = fa1.x + fa1.y + fa1.z;
        float p1 = fa1.w + fb1.x + fb1.y;
        float p2 = fb1.z + fb1.w + fc1.x;
        float p3 = fc1.y + fc1.z + fc1.w;
        float q0 = fa2.x + fa2.y + fa2.z;
        float q1 = fa2.w + fb2.x + fb2.y;
        float q2 = fb2.z + fb2.w + fc2.x;
        float q3 = fc2.y + fc2.z + fc2.w;

        s0 += (i1.x == 0) ? p0 : 0.f;  c0 += (i1.x == 0);
        s1 += (i1.x == 1) ? p0 : 0.f;  c1 += (i1.x == 1);
        s2 += (i1.x == 2) ? p0 : 0.f;  c2 += (i1.x == 2);
        s0 += (i1.y == 0) ? p1 : 0.f;  c0 += (i1.y == 0);
        s1 += (i1.y == 1) ? p1 : 0.f;  c1 += (i1.y == 1);
        s2 += (i1.y == 2) ? p1 : 0.f;  c2 += (i1.y == 2);
        s0 += (i1.z == 0) ? p2 : 0.f;  c0 += (i1.z == 0);
        s1 += (i1.z == 1) ? p2 : 0.f;  c1 += (i1.z == 1);
        s2 += (i1.z == 2) ? p2 : 0.f;  c2 += (i1.z == 2);
        s0 += (i1.w == 0) ? p3 : 0.f;  c0 += (i1.w == 0);
        s1 += (i1.w == 1) ? p3 : 0.f;  c1 += (i1.w == 1);
        s2 += (i1.w == 2) ? p3 : 0.f;  c2 += (i1.w == 2);

        s0 += (i2.x == 0) ? q0 : 0.f;  c0 += (i2.x == 0);
        s1 += (i2.x == 1) ? q0 : 0.f;  c1 += (i2.x == 1);
        s2 += (i2.x == 2) ? q0 : 0.f;  c2 += (i2.x == 2);
        s0 += (i2.y == 0) ? q1 : 0.f;  c0 += (i2.y == 0);
        s1 += (i2.y == 1) ? q1 : 0.f;  c1 += (i2.y == 1);
        s2 += (i2.y == 2) ? q1 : 0.f;  c2 += (i2.y == 2);
        s0 += (i2.z == 0) ? q2 : 0.f;  c0 += (i2.z == 0);
        s1 += (i2.z == 1) ? q2 : 0.f;  c1 += (i2.z == 1);
        s2 += (i2.z == 2) ? q2 : 0.f;  c2 += (i2.z == 2);
        s0 += (i2.w == 0) ? q3 : 0.f;  c0 += (i2.w == 0);
        s1 += (i2.w == 1) ? q3 : 0.f;  c1 += (i2.w == 1);
        s2 += (i2.w == 2) ? q3 : 0.f;  c2 += (i2.w == 2);
    }
    // leftover single group (at most one per thread)
    if (base < ngroups) {
        const int g = base;
        int4   ii = __ldcs(&inst4[(size_t)g]);
        float4 fa = __ldcs(&feats4[(size_t)3 * g + 0]);
        float4 fb = __ldcs(&feats4[(size_t)3 * g + 1]);
        float4 fc = __ldcs(&feats4[(size_t)3 * g + 2]);
        g_packed[g] = (unsigned char)(ii.x | (ii.y << 2) | (ii.z << 4) | (ii.w << 6));
        float p0 = fa.x + fa.y + fa.z;
        float p1 = fa.w + fb.x + fb.y;
        float p2 = fb.z + fb.w + fc.x;
        float p3 = fc.y + fc.z + fc.w;
        s0 += (ii.x == 0) ? p0 : 0.f;  c0 += (ii.x == 0);
        s1 += (ii.x == 1) ? p0 : 0.f;  c1 += (ii.x == 1);
        s2 += (ii.x == 2) ? p0 : 0.f;  c2 += (ii.x == 2);
        s0 += (ii.y == 0) ? p1 : 0.f;  c0 += (ii.y == 0);
        s1 += (ii.y == 1) ? p1 : 0.f;  c1 += (ii.y == 1);
        s2 += (ii.y == 2) ? p1 : 0.f;  c2 += (ii.y == 2);
        s0 += (ii.z == 0) ? p2 : 0.f;  c0 += (ii.z == 0);
        s1 += (ii.z == 1) ? p2 : 0.f;  c1 += (ii.z == 1);
        s2 += (ii.z == 2) ? p2 : 0.f;  c2 += (ii.z == 2);
        s0 += (ii.w == 0) ? p3 : 0.f;  c0 += (ii.w == 0);
        s1 += (ii.w == 1) ? p3 : 0.f;  c1 += (ii.w == 1);
        s2 += (ii.w == 2) ? p3 : 0.f;  c2 += (ii.w == 2);
    }

    // scalar tail (npix % 4)
    if (tid < rem) {
        size_t p = (size_t)ngroups * 4 + tid;
        int cls = inst[p];
        float v = feats[3 * p + 0] + feats[3 * p + 1] + feats[3 * p + 2];
        s0 += (cls == 0) ? v : 0.f;  c0 += (cls == 0);
        s1 += (cls == 1) ? v : 0.f;  c1 += (cls == 1);
        s2 += (cls == 2) ? v : 0.f;  c2 += (cls == 2);
    }

    // warp reduce
    #pragma unroll
    for (int off = 16; off > 0; off >>= 1) {
        s0 += __shfl_down_sync(0xFFFFFFFFu, s0, off);
        s1 += __shfl_down_sync(0xFFFFFFFFu, s1, off);
        s2 += __shfl_down_sync(0xFFFFFFFFu, s2, off);
        c0 += __shfl_down_sync(0xFFFFFFFFu, c0, off);
        c1 += __shfl_down_sync(0xFFFFFFFFu, c1, off);
        c2 += __shfl_down_sync(0xFFFFFFFFu, c2, off);
    }

    __shared__ float sh_s[3][8];
    __shared__ int   sh_c[3][8];
    int lane = threadIdx.x & 31;
    int wid  = threadIdx.x >> 5;
    if (lane == 0) {
        sh_s[0][wid] = s0; sh_s[1][wid] = s1; sh_s[2][wid] = s2;
        sh_c[0][wid] = c0; sh_c[1][wid] = c1; sh_c[2][wid] = c2;
    }
    __syncthreads();

    if (threadIdx.x < 3) {
        int cls = threadIdx.x;
        float     fs = 0.f;
        long long ic = 0;
        int nwarps = blockDim.x >> 5;
        for (int w = 0; w < nwarps; w++) { fs += sh_s[cls][w]; ic += sh_c[cls][w]; }
        atomicAdd(&g_sum[cls], (double)fs);
        atomicAdd(&g_cnt[cls], (unsigned long long)ic);
    }
}

// Finalize: compute means, then RESET accumulators so the next replay of the
// captured graph starts from zero (replaces the separate zero_kernel).
__global__ void finalize_kernel() {
    if (threadIdx.x < 3) {
        int c = threadIdx.x;
        double denom = 3.0 * (double)g_cnt[c];   // count includes the 3 channels
        g_mean[c] = (float)(g_sum[c] / denom);
        g_sum[c] = 0.0;
        g_cnt[c] = 0ULL;
    }
}

// Scatter: one float4 per thread per iteration -> fully coalesced STG.128.
// Classes come from the packed 2-bit array (4 MiB, L2-hot from reduce).
// (Kept identical to Round 9 — pinned at the DRAM write ceiling.)
__global__ void __launch_bounds__(256) scatter_kernel(
        float4* __restrict__ out4,
        const int* __restrict__ inst,
        float* __restrict__ out,
        int nf4, int ngroups, int rem) {
    const float m0 = g_mean[0];
    const float m1 = g_mean[1];
    const float m2 = g_mean[2];

    const int tid    = blockIdx.x * blockDim.x + threadIdx.x;
    const int stride = gridDim.x * blockDim.x;

    for (int f = tid; f < nf4; f += stride) {
        int g = f / 3;                 // pixel-group (4 pixels, 12 floats, 3 float4s)
        int s = f - 3 * g;             // which float4 within the group: 0,1,2
        unsigned int b = g_packed[g];

        // float j of this float4 belongs to local pixel (4s + j) / 3
        int base = 4 * s;
        float v[4];
        #pragma unroll
        for (int j = 0; j < 4; j++) {
            int pl  = (base + j) / 3;
            int cls = (b >> (2 * pl)) & 3;
            v[j] = (cls == 0) ? m0 : ((cls == 1) ? m1 : m2);
        }
        __stcs(&out4[(size_t)f], make_float4(v[0], v[1], v[2], v[3]));
    }

    if (tid < rem) {
        size_t p = (size_t)ngroups * 4 + tid;
        int cls = inst[p];
        float m = (cls == 0) ? m0 : ((cls == 1) ? m1 : m2);
        out[3 * p + 0] = m;
        out[3 * p + 1] = m;
        out[3 * p + 2] = m;
    }
}

extern "C" void kernel_launch(void* const* d_in, const int* in_sizes, int n_in,
                              void* d_out, int out_size) {
    const float* feats = (const float*)d_in[0];
    const int*   inst  = (const int*)d_in[1];
    float*       out   = (float*)d_out;

    const int npix    = in_sizes[1];      // one inst entry per pixel
    const int ngroups = npix >> 2;        // groups of 4 pixels
    const int rem     = npix & 3;
    const int nf4     = 3 * ngroups;      // float4s covered by packed groups (exact)

    const int threads = 256;
    const int blocks  = 1216;             // 152 SMs * 8 CTAs; grid-stride covers the rest

    reduce_kernel<<<blocks, threads>>>((const float4*)feats, (const int4*)inst,
                                       feats, inst, ngroups, rem);
    finalize_kernel<<<1, 32>>>();
    scatter_kernel<<<blocks, threads>>>((float4*)out, inst, out, nf4, ngroups, rem);
}

// round 16
// speedup vs baseline: 1.2713x; 1.0087x over previous
#include <cuda_runtime.h>
#include <cuda_bf16.h>

// Scratch (no cudaMalloc). Statically zero-initialized at module load;
// finalize_kernel re-zeroes accumulators after use so every graph replay
// starts from a clean state.
__device__ double             g_sum[3];
__device__ unsigned long long g_cnt[3];
__device__ float              g_mean[3];
// 2-bit classes packed 4 pixels/byte: max 16M pixels -> 4 MiB (L2-resident).
__device__ unsigned char      g_packed[4 * 1024 * 1024];

// Reduce: per-class global sums + counts, and emit packed 2-bit classes.
// Two groups per iteration, spaced `stride` apart: 8 independent LDG.128s
// in flight (MLP 8), each warp-coalesced.
// __launch_bounds__(256, 6): cap regs at 42 -> 6 CTAs/SM (was 44 regs / 5 CTAs,
// occ 54%). More resident warps -> more loads in flight.
__global__ void __launch_bounds__(256, 6) reduce_kernel(
        const float4* __restrict__ feats4,
        const int4*  __restrict__ inst4,
        const float* __restrict__ feats,
        const int*   __restrict__ inst,
        int ngroups, int rem) {
    float s0 = 0.f, s1 = 0.f, s2 = 0.f;
    int   c0 = 0,   c1 = 0,   c2 = 0;

    const int tid     = blockIdx.x * blockDim.x + threadIdx.x;
    const int stride  = gridDim.x * blockDim.x;
    const int stride2 = 2 * stride;

    int base = tid;
    for (; base + stride < ngroups; base += stride2) {
        const int g1 = base, g2 = base + stride;
        // issue all 8 loads up front (independent -> MLP 8)
        int4   i1  = __ldcs(&inst4[(size_t)g1]);
        float4 fa1 = __ldcs(&feats4[(size_t)3 * g1 + 0]);
        float4 fb1 = __ldcs(&feats4[(size_t)3 * g1 + 1]);
        float4 fc1 = __ldcs(&feats4[(size_t)3 * g1 + 2]);
        int4   i2  = __ldcs(&inst4[(size_t)g2]);
        float4 fa2 = __ldcs(&feats4[(size_t)3 * g2 + 0]);
        float4 fb2 = __ldcs(&feats4[(size_t)3 * g2 + 1]);
        float4 fc2 = __ldcs(&feats4[(size_t)3 * g2 + 2]);

        g_packed[g1] = (unsigned char)(i1.x | (i1.y << 2) | (i1.z << 4) | (i1.w << 6));
        g_packed[g2] = (unsigned char)(i2.x | (i2.y << 2) | (i2.z << 4) | (i2.w << 6));

        float p0 = fa1.x + fa1.y + fa1.z;
        float p1 = fa1.w + fb1.x + fb1.y;
        float p2 = fb1.z + fb1.w + fc1.x;
        float p3 = fc1.y + fc1.z + fc1.w;
        float q0 = fa2.x + fa2.y + fa2.z;
        float q1 = fa2.w + fb2.x + fb2.y;
        float q2 = fb2.z + fb2.w + fc2.x;
        float q3 = fc2.y + fc2.z + fc2.w;

        s0 += (i1.x == 0) ? p0 : 0.f;  c0 += (i1.x == 0);
        s1 += (i1.x == 1) ? p0 : 0.f;  c1 += (i1.x == 1);
        s2 += (i1.x == 2) ? p0 : 0.f;  c2 += (i1.x == 2);
        s0 += (i1.y == 0) ? p1 : 0.f;  c0 += (i1.y == 0);
        s1 += (i1.y == 1) ? p1 : 0.f;  c1 += (i1.y == 1);
        s2 += (i1.y == 2) ? p1 : 0.f;  c2 += (i1.y == 2);
        s0 += (i1.z == 0) ? p2 : 0.f;  c0 += (i1.z == 0);
        s1 += (i1.z == 1) ? p2 : 0.f;  c1 += (i1.z == 1);
        s2 += (i1.z == 2) ? p2 : 0.f;  c2 += (i1.z == 2);
        s0 += (i1.w == 0) ? p3 : 0.f;  c0 += (i1.w == 0);
        s1 += (i1.w == 1) ? p3 : 0.f;  c1 += (i1.w == 1);
        s2 += (i1.w == 2) ? p3 : 0.f;  c2 += (i1.w == 2);

        s0 += (i2.x == 0) ? q0 : 0.f;  c0 += (i2.x == 0);
        s1 += (i2.x == 1) ? q0 : 0.f;  c1 += (i2.x == 1);
        s2 += (i2.x == 2) ? q0 : 0.f;  c2 += (i2.x == 2);
        s0 += (i2.y == 0) ? q1 : 0.f;  c0 += (i2.y == 0);
        s1 += (i2.y == 1) ? q1 : 0.f;  c1 += (i2.y == 1);
        s2 += (i2.y == 2) ? q1 : 0.f;  c2 += (i2.y == 2);
        s0 += (i2.z == 0) ? q2 : 0.f;  c0 += (i2.z == 0);
        s1 += (i2.z == 1) ? q2 : 0.f;  c1 += (i2.z == 1);
        s2 += (i2.z == 2) ? q2 : 0.f;  c2 += (i2.z == 2);
        s0 += (i2.w == 0) ? q3 : 0.f;  c0 += (i2.w == 0);
        s1 += (i2.w == 1) ? q3 : 0.f;  c1 += (i2.w == 1);
        s2 += (i2.w == 2) ? q3 : 0.f;  c2 += (i2.w == 2);
    }
    // leftover single group (at most one per thread)
    if (base < ngroups) {
        const int g = base;
        int4   ii = __ldcs(&inst4[(size_t)g]);
        float4 fa = __ldcs(&feats4[(size_t)3 * g + 0]);
        float4 fb = __ldcs(&feats4[(size_t)3 * g + 1]);
        float4 fc = __ldcs(&feats4[(size_t)3 * g + 2]);
        g_packed[g] = (unsigned char)(ii.x | (ii.y << 2) | (ii.z << 4) | (ii.w << 6));
        float p0 = fa.x + fa.y + fa.z;
        float p1 = fa.w + fb.x + fb.y;
        float p2 = fb.z + fb.w + fc.x;
        float p3 = fc.y + fc.z + fc.w;
        s0 += (ii.x == 0) ? p0 : 0.f;  c0 += (ii.x == 0);
        s1 += (ii.x == 1) ? p0 : 0.f;  c1 += (ii.x == 1);
        s2 += (ii.x == 2) ? p0 : 0.f;  c2 += (ii.x == 2);
        s0 += (ii.y == 0) ? p1 : 0.f;  c0 += (ii.y == 0);
        s1 += (ii.y == 1) ? p1 : 0.f;  c1 += (ii.y == 1);
        s2 += (ii.y == 2) ? p1 : 0.f;  c2 += (ii.y == 2);
        s0 += (ii.z == 0) ? p2 : 0.f;  c0 += (ii.z == 0);
        s1 += (ii.z == 1) ? p2 : 0.f;  c1 += (ii.z == 1);
        s2 += (ii.z == 2) ? p2 : 0.f;  c2 += (ii.z == 2);
        s0 += (ii.w == 0) ? p3 : 0.f;  c0 += (ii.w == 0);
        s1 += (ii.w == 1) ? p3 : 0.f;  c1 += (ii.w == 1);
        s2 += (ii.w == 2) ? p3 : 0.f;  c2 += (ii.w == 2);
    }

    // scalar tail (npix % 4)
    if (tid < rem) {
        size_t p = (size_t)ngroups * 4 + tid;
        int cls = inst[p];
        float v = feats[3 * p + 0] + feats[3 * p + 1] + feats[3 * p + 2];
        s0 += (cls == 0) ? v : 0.f;  c0 += (cls == 0);
        s1 += (cls == 1) ? v : 0.f;  c1 += (cls == 1);
        s2 += (cls == 2) ? v : 0.f;  c2 += (cls == 2);
    }

    // warp reduce
    #pragma unroll
    for (int off = 16; off > 0; off >>= 1) {
        s0 += __shfl_down_sync(0xFFFFFFFFu, s0, off);
        s1 += __shfl_down_sync(0xFFFFFFFFu, s1, off);
        s2 += __shfl_down_sync(0xFFFFFFFFu, s2, off);
        c0 += __shfl_down_sync(0xFFFFFFFFu, c0, off);
        c1 += __shfl_down_sync(0xFFFFFFFFu, c1, off);
        c2 += __shfl_down_sync(0xFFFFFFFFu, c2, off);
    }

    __shared__ float sh_s[3][8];
    __shared__ int   sh_c[3][8];
    int lane = threadIdx.x & 31;
    int wid  = threadIdx.x >> 5;
    if (lane == 0) {
        sh_s[0][wid] = s0; sh_s[1][wid] = s1; sh_s[2][wid] = s2;
        sh_c[0][wid] = c0; sh_c[1][wid] = c1; sh_c[2][wid] = c2;
    }
    __syncthreads();

    if (threadIdx.x < 3) {
        int cls = threadIdx.x;
        float     fs = 0.f;
        long long ic = 0;
        int nwarps = blockDim.x >> 5;
        for (int w = 0; w < nwarps; w++) { fs += sh_s[cls][w]; ic += sh_c[cls][w]; }
        atomicAdd(&g_sum[cls], (double)fs);
        atomicAdd(&g_cnt[cls], (unsigned long long)ic);
    }
}

// Finalize: compute means, then RESET accumulators so the next replay of the
// captured graph starts from zero.
__global__ void finalize_kernel() {
    if (threadIdx.x < 3) {
        int c = threadIdx.x;
        double denom = 3.0 * (double)g_cnt[c];   // count includes the 3 channels
        g_mean[c] = (float)(g_sum[c] / denom);
        g_sum[c] = 0.0;
        g_cnt[c] = 0ULL;
    }
}

// Scatter: one float4 per thread per iteration -> fully coalesced STG.128.
// 2-way unrolled (spaced by stride): two independent store chains in flight.
// Classes come from the packed 2-bit array (4 MiB, L2-hot from reduce).
__global__ void __launch_bounds__(256) scatter_kernel(
        float4* __restrict__ out4,
        const int* __restrict__ inst,
        float* __restrict__ out,
        int nf4, int ngroups, int rem) {
    const float m0 = g_mean[0];
    const float m1 = g_mean[1];
    const float m2 = g_mean[2];

    const int tid     = blockIdx.x * blockDim.x + threadIdx.x;
    const int stride  = gridDim.x * blockDim.x;
    const int stride2 = 2 * stride;

    int f = tid;
    for (; f + stride < nf4; f += stride2) {
        const int f1 = f, f2 = f + stride;
        int g1 = f1 / 3, s1i = f1 - 3 * g1;
        int g2 = f2 / 3, s2i = f2 - 3 * g2;
        unsigned int b1 = g_packed[g1];
        unsigned int b2 = g_packed[g2];

        int base1 = 4 * s1i, base2 = 4 * s2i;
        float v1[4], v2[4];
        #pragma unroll
        for (int j = 0; j < 4; j++) {
            int pl1  = (base1 + j) / 3;
            int cls1 = (b1 >> (2 * pl1)) & 3;
            v1[j] = (cls1 == 0) ? m0 : ((cls1 == 1) ? m1 : m2);
            int pl2  = (base2 + j) / 3;
            int cls2 = (b2 >> (2 * pl2)) & 3;
            v2[j] = (cls2 == 0) ? m0 : ((cls2 == 1) ? m1 : m2);
        }
        __stcs(&out4[(size_t)f1], make_float4(v1[0], v1[1], v1[2], v1[3]));
        __stcs(&out4[(size_t)f2], make_float4(v2[0], v2[1], v2[2], v2[3]));
    }
    if (f < nf4) {
        int g = f / 3;
        int s = f - 3 * g;
        unsigned int b = g_packed[g];
        int base = 4 * s;
        float v[4];
        #pragma unroll
        for (int j = 0; j < 4; j++) {
            int pl  = (base + j) / 3;
            int cls = (b >> (2 * pl)) & 3;
            v[j] = (cls == 0) ? m0 : ((cls == 1) ? m1 : m2);
        }
        __stcs(&out4[(size_t)f], make_float4(v[0], v[1], v[2], v[3]));
    }

    if (tid < rem) {
        size_t p = (size_t)ngroups * 4 + tid;
        int cls = inst[p];
        float m = (cls == 0) ? m0 : ((cls == 1) ? m1 : m2);
        out[3 * p + 0] = m;
        out[3 * p + 1] = m;
        out[3 * p + 2] = m;
    }
}

extern "C" void kernel_launch(void* const* d_in, const int* in_sizes, int n_in,
                              void* d_out, int out_size) {
    const float* feats = (const float*)d_in[0];
    const int*   inst  = (const int*)d_in[1];
    float*       out   = (float*)d_out;

    const int npix    = in_sizes[1];      // one inst entry per pixel
    const int ngroups = npix >> 2;        // groups of 4 pixels
    const int rem     = npix & 3;
    const int nf4     = 3 * ngroups;      // float4s covered by packed groups (exact)

    const int threads = 256;
    const int blocks  = 1216;             // 152 SMs * 8 CTAs; grid-stride covers the rest

    reduce_kernel<<<blocks, threads>>>((const float4*)feats, (const int4*)inst,
                                       feats, inst, ngroups, rem);
    finalize_kernel<<<1, 32>>>();
    scatter_kernel<<<blocks, threads>>>((float4*)out, inst, out, nf4, ngroups, rem);
}